// round 2
// baseline (speedup 1.0000x reference)
#include <cuda_runtime.h>
#include <math.h>

#define BB 2
#define SS 1024
#define DMODEL 1024
#define HH 16
#define DD 64
#define PP 512               // 2*SPAN
#define BH (BB*HH)
#define INV_SCALE 0.07216878364870323f   // 1/sqrt(192)

// ---------------- scratch (static device memory; no allocs allowed) ----------
__device__ float g_Q[BB*SS*DMODEL];
__device__ float g_K[BB*SS*DMODEL];
__device__ float g_V[BB*SS*DMODEL];
__device__ float g_posK[PP*DMODEL];
__device__ float g_posQ[PP*DMODEL];
__device__ float g_C2P[(size_t)BH*SS*PP];
__device__ float g_P2C[(size_t)BH*SS*PP];
__device__ float g_S[(size_t)BH*SS*SS];
__device__ float g_ctx[BB*SS*DMODEL];
__device__ float g_H[BB*SS*DMODEL];
__device__ int   g_idx[2047];

// ---------------- idx table: clip(bucket(delta)+256, 0, 511) -----------------
__global__ void build_idx_kernel() {
    int t = blockIdx.x * blockDim.x + threadIdx.x;
    if (t >= 2047) return;
    int rel = t - 1023;
    int bucket;
    if (rel > -128 && rel < 128) {
        bucket = rel;
    } else {
        double abs_pos = fabs((double)rel);
        if (abs_pos <= 128.0) {
            bucket = rel;
        } else {
            int sgn = (rel > 0) - (rel < 0);
            double lp = ceil(log(abs_pos / 128.0) / log(511.0 / 128.0) * 127.0) + 128.0;
            bucket = (int)lp * sgn;
        }
    }
    int i1 = bucket + 256;
    i1 = i1 < 0 ? 0 : (i1 > 511 ? 511 : i1);
    g_idx[t] = i1;
}

// ---------------- 128x128x8 SGEMM, C = A[M,K]@W[K,N] + bias (+resid) ---------
__global__ __launch_bounds__(256) void sgemm128(
    const float* __restrict__ A, const float* __restrict__ W,
    const float* __restrict__ bias, const float* __restrict__ resid,
    float* __restrict__ C, int M, int N, int K)
{
    __shared__ float sA[8][128];
    __shared__ float sB[8][128];
    int t = threadIdx.x;
    int m0 = blockIdx.y * 128, n0 = blockIdx.x * 128;
    int arow = t >> 1, acol = (t & 1) * 4;
    int brow = t >> 5, bcol = (t & 31) * 4;
    int tx8 = (t & 15) * 8, ty8 = (t >> 4) * 8;

    float acc[8][8];
    #pragma unroll
    for (int i = 0; i < 8; i++)
        #pragma unroll
        for (int j = 0; j < 8; j++) acc[i][j] = 0.f;

    for (int k0 = 0; k0 < K; k0 += 8) {
        float4 av = *(const float4*)(A + (size_t)(m0 + arow) * K + k0 + acol);
        float4 bv = *(const float4*)(W + (size_t)(k0 + brow) * N + n0 + bcol);
        __syncthreads();
        sA[acol + 0][arow] = av.x;
        sA[acol + 1][arow] = av.y;
        sA[acol + 2][arow] = av.z;
        sA[acol + 3][arow] = av.w;
        *(float4*)&sB[brow][bcol] = bv;
        __syncthreads();
        #pragma unroll
        for (int kk = 0; kk < 8; kk++) {
            float ra[8], rb[8];
            *(float4*)(ra)     = *(const float4*)&sA[kk][ty8];
            *(float4*)(ra + 4) = *(const float4*)&sA[kk][ty8 + 4];
            *(float4*)(rb)     = *(const float4*)&sB[kk][tx8];
            *(float4*)(rb + 4) = *(const float4*)&sB[kk][tx8 + 4];
            #pragma unroll
            for (int i = 0; i < 8; i++)
                #pragma unroll
                for (int j = 0; j < 8; j++)
                    acc[i][j] += ra[i] * rb[j];
        }
    }

    int cm = m0 + ty8, cn = n0 + tx8;
    #pragma unroll
    for (int i = 0; i < 8; i++) {
        size_t rbase = (size_t)(cm + i) * N + cn;
        #pragma unroll
        for (int j = 0; j < 8; j++) {
            float v = acc[i][j] + bias[cn + j];
            if (resid) v += resid[rbase + j];
            C[rbase + j] = v;
        }
    }
}

// ------------- C2P / P2C: Out[bh,q,p] = sum_d X[b,q,h,d]*Ppos[p,h,d] ---------
__global__ __launch_bounds__(256) void posdot_kernel(
    const float* __restrict__ X, const float* __restrict__ Ppos,
    float* __restrict__ Out)
{
    __shared__ float sX[64][68];
    __shared__ float sP[64][68];
    int bh = blockIdx.z, b = bh >> 4, h = bh & 15;
    int q0 = blockIdx.y * 64, p0 = blockIdx.x * 64;
    int t = threadIdx.x;
    const float* Xb = X + ((size_t)(b * SS + q0)) * DMODEL + h * DD;
    const float* Pb = Ppos + (size_t)p0 * DMODEL + h * DD;
    #pragma unroll
    for (int i = 0; i < 16; i++) {
        int lin = t + i * 256;
        int r = lin >> 6, d = lin & 63;
        sX[d][r] = Xb[(size_t)r * DMODEL + d];
        sP[d][r] = Pb[(size_t)r * DMODEL + d];
    }
    __syncthreads();
    int tx = t & 15, ty = t >> 4;
    float acc[4][4] = {};
    #pragma unroll
    for (int d = 0; d < 64; d++) {
        float ra[4], rb[4];
        *(float4*)ra = *(const float4*)&sX[d][ty * 4];
        *(float4*)rb = *(const float4*)&sP[d][tx * 4];
        #pragma unroll
        for (int i = 0; i < 4; i++)
            #pragma unroll
            for (int j = 0; j < 4; j++) acc[i][j] += ra[i] * rb[j];
    }
    #pragma unroll
    for (int i = 0; i < 4; i++) {
        size_t rbase = ((size_t)bh * SS + q0 + ty * 4 + i) * PP + p0;
        #pragma unroll
        for (int j = 0; j < 4; j++) Out[rbase + tx * 4 + j] = acc[i][j];
    }
}

// ---- scores: (QK + C2P[q,idx(q-k)] + P2C[k,idx(q-k)]) * INV_SCALE -----------
__global__ __launch_bounds__(256) void scores_kernel()
{
    __shared__ float sQ[64][68];
    __shared__ float sK[64][68];
    __shared__ int s_idx[128];
    int bh = blockIdx.z, b = bh >> 4, h = bh & 15;
    int q0 = blockIdx.y * 64, k0 = blockIdx.x * 64;
    int t = threadIdx.x;
    if (t < 127) s_idx[t] = g_idx[q0 - k0 + 960 + t];
    #pragma unroll
    for (int i = 0; i < 16; i++) {
        int lin = t + i * 256;
        int r = lin >> 6, d = lin & 63;
        sQ[d][r] = g_Q[((size_t)(b * SS + q0 + r)) * DMODEL + h * DD + d];
        sK[d][r] = g_K[((size_t)(b * SS + k0 + r)) * DMODEL + h * DD + d];
    }
    __syncthreads();
    int tx = t & 15, ty = t >> 4;
    float acc[4][4] = {};
    #pragma unroll
    for (int d = 0; d < 64; d++) {
        float ra[4], rb[4];
        *(float4*)ra = *(const float4*)&sQ[d][ty * 4];
        *(float4*)rb = *(const float4*)&sK[d][tx * 4];
        #pragma unroll
        for (int i = 0; i < 4; i++)
            #pragma unroll
            for (int j = 0; j < 4; j++) acc[i][j] += ra[i] * rb[j];
    }
    #pragma unroll
    for (int i = 0; i < 4; i++) {
        int q = q0 + ty * 4 + i;
        const float* c2p = g_C2P + ((size_t)bh * SS + q) * PP;
        float* srow = g_S + ((size_t)bh * SS + q) * SS;
        #pragma unroll
        for (int j = 0; j < 4; j++) {
            int k = k0 + tx * 4 + j;
            int id = s_idx[(ty * 4 + i) - (tx * 4 + j) + 63];
            float v = (acc[i][j] + c2p[id]
                       + g_P2C[((size_t)bh * SS + k) * PP + id]) * INV_SCALE;
            srow[k] = v;
        }
    }
}

// ---------------- masked softmax over k, in place in g_S ---------------------
__global__ __launch_bounds__(256) void softmax_kernel(const int* __restrict__ am)
{
    __shared__ float red[256];
    int row = blockIdx.x;              // bh*S + q
    int bh = row >> 10, q = row & 1023;
    int b = bh >> 4;
    float* srow = g_S + (size_t)row * SS;
    const int* mrow = am + ((size_t)(b * SS + q)) * SS;
    int t = threadIdx.x;
    float x[4]; int m[4];
    float mx = -3.0e38f;
    #pragma unroll
    for (int i = 0; i < 4; i++) {
        int k = t + i * 256;
        m[i] = mrow[k];
        x[i] = m[i] ? srow[k] : -3.0e38f;
        mx = fmaxf(mx, x[i]);
    }
    red[t] = mx; __syncthreads();
    for (int s = 128; s; s >>= 1) { if (t < s) red[t] = fmaxf(red[t], red[t + s]); __syncthreads(); }
    mx = red[0]; __syncthreads();
    float sm = 0.f;
    #pragma unroll
    for (int i = 0; i < 4; i++) {
        x[i] = m[i] ? __expf(x[i] - mx) : 0.f;
        sm += x[i];
    }
    red[t] = sm; __syncthreads();
    for (int s = 128; s; s >>= 1) { if (t < s) red[t] += red[t + s]; __syncthreads(); }
    float inv = red[0] > 0.f ? 1.f / red[0] : 0.f;
    #pragma unroll
    for (int i = 0; i < 4; i++) srow[t + i * 256] = x[i] * inv;
}

// ---------------- ctx = probs @ V  (per head, N = 64 full) -------------------
__global__ __launch_bounds__(256) void pv_kernel()
{
    __shared__ float sP[64][68];
    __shared__ float sV[64][68];
    int bh = blockIdx.z, b = bh >> 4, h = bh & 15;
    int q0 = blockIdx.y * 64;
    int t = threadIdx.x;
    int tx = t & 15, ty = t >> 4;
    float acc[4][4] = {};
    for (int k0 = 0; k0 < SS; k0 += 64) {
        __syncthreads();
        #pragma unroll
        for (int i = 0; i < 16; i++) {
            int lin = t + i * 256;
            int r = lin >> 6, c = lin & 63;
            sP[c][r] = g_S[((size_t)bh * SS + q0 + r) * SS + k0 + c];
            sV[r][c] = g_V[((size_t)(b * SS + k0 + r)) * DMODEL + h * DD + c];
        }
        __syncthreads();
        #pragma unroll
        for (int kk = 0; kk < 64; kk++) {
            float rp[4], rv[4];
            *(float4*)rp = *(const float4*)&sP[kk][ty * 4];
            *(float4*)rv = *(const float4*)&sV[kk][tx * 4];
            #pragma unroll
            for (int i = 0; i < 4; i++)
                #pragma unroll
                for (int j = 0; j < 4; j++) acc[i][j] += rp[i] * rv[j];
        }
    }
    #pragma unroll
    for (int i = 0; i < 4; i++)
        #pragma unroll
        for (int j = 0; j < 4; j++)
            g_ctx[((size_t)(b * SS + q0 + ty * 4 + i)) * DMODEL + h * DD + tx * 4 + j] = acc[i][j];
}

// ---------------- layernorm of g_H, write to output --------------------------
__global__ __launch_bounds__(256) void ln_kernel(
    const float* __restrict__ lw, const float* __restrict__ lb,
    float* __restrict__ out)
{
    __shared__ float red[256];
    __shared__ float red2[256];
    int r = blockIdx.x, t = threadIdx.x;
    const float* x = g_H + (size_t)r * DMODEL;
    float s = 0.f, s2 = 0.f;
    #pragma unroll
    for (int i = 0; i < 4; i++) {
        float v = x[t + i * 256];
        s += v; s2 += v * v;
    }
    red[t] = s; red2[t] = s2; __syncthreads();
    for (int st = 128; st; st >>= 1) {
        if (t < st) { red[t] += red[t + st]; red2[t] += red2[t + st]; }
        __syncthreads();
    }
    float mu = red[0] * (1.f / DMODEL);
    float var = red2[0] * (1.f / DMODEL) - mu * mu;
    float inv = rsqrtf(var + 1e-7f);
    #pragma unroll
    for (int i = 0; i < 4; i++) {
        int c = t + i * 256;
        out[(size_t)r * DMODEL + c] = (x[c] - mu) * inv * lw[c] + lb[c];
    }
}

// ---------------- launch ------------------------------------------------------
extern "C" void kernel_launch(void* const* d_in, const int* in_sizes, int n_in,
                              void* d_out, int out_size)
{
    const float* hs  = (const float*)d_in[0];
    const float* rel = (const float*)d_in[1];
    const float* Wq  = (const float*)d_in[2];  const float* bq = (const float*)d_in[3];
    const float* Wk  = (const float*)d_in[4];  const float* bk = (const float*)d_in[5];
    const float* Wv  = (const float*)d_in[6];  const float* bv = (const float*)d_in[7];
    const float* Wo  = (const float*)d_in[8];  const float* bo = (const float*)d_in[9];
    const float* lw  = (const float*)d_in[10]; const float* lb = (const float*)d_in[11];
    const int*   am  = (const int*)d_in[12];
    float* out = (float*)d_out;

    float *Q_, *K_, *V_, *PK_, *PQ_, *C2P_, *P2C_, *CTX_, *Hb_;
    cudaGetSymbolAddress((void**)&Q_,   g_Q);
    cudaGetSymbolAddress((void**)&K_,   g_K);
    cudaGetSymbolAddress((void**)&V_,   g_V);
    cudaGetSymbolAddress((void**)&PK_,  g_posK);
    cudaGetSymbolAddress((void**)&PQ_,  g_posQ);
    cudaGetSymbolAddress((void**)&C2P_, g_C2P);
    cudaGetSymbolAddress((void**)&P2C_, g_P2C);
    cudaGetSymbolAddress((void**)&CTX_, g_ctx);
    cudaGetSymbolAddress((void**)&Hb_,  g_H);

    build_idx_kernel<<<8, 256>>>();

    // projections
    sgemm128<<<dim3(8, 16), 256>>>(hs,  Wq, bq, nullptr, Q_,  BB*SS, DMODEL, DMODEL);
    sgemm128<<<dim3(8, 16), 256>>>(hs,  Wk, bk, nullptr, K_,  BB*SS, DMODEL, DMODEL);
    sgemm128<<<dim3(8, 16), 256>>>(hs,  Wv, bv, nullptr, V_,  BB*SS, DMODEL, DMODEL);
    sgemm128<<<dim3(8, 4),  256>>>(rel, Wk, bk, nullptr, PK_, PP,    DMODEL, DMODEL);
    sgemm128<<<dim3(8, 4),  256>>>(rel, Wq, bq, nullptr, PQ_, PP,    DMODEL, DMODEL);

    // disentangled bias tables
    posdot_kernel<<<dim3(PP/64, SS/64, BH), 256>>>(Q_, PK_, C2P_);
    posdot_kernel<<<dim3(PP/64, SS/64, BH), 256>>>(K_, PQ_, P2C_);

    // scores + bias gather, softmax, probs @ V
    scores_kernel<<<dim3(SS/64, SS/64, BH), 256>>>();
    softmax_kernel<<<BH*SS, 256>>>(am);
    pv_kernel<<<dim3(1, SS/64, BH), 256>>>();

    // output projection + residual, then layernorm
    sgemm128<<<dim3(8, 16), 256>>>(CTX_, Wo, bo, hs, Hb_, BB*SS, DMODEL, DMODEL);
    ln_kernel<<<BB*SS, 256>>>(lw, lb, out);
}

// round 3
// speedup vs baseline: 1.4554x; 1.4554x over previous
#include <cuda_runtime.h>
#include <math.h>
#include <stdint.h>

#define BB 2
#define SS 1024
#define DMODEL 1024
#define HH 16
#define DD 64
#define PP 512               // 2*SPAN
#define BH (BB*HH)
#define INV_SCALE 0.07216878364870323f   // 1/sqrt(192)

// ---------------- scratch (static device memory; no allocs allowed) ----------
// head-major: [BH][S][64] for Q,K,V ; [H][512][64] for posK,posQ
__device__ float g_Q[BH*SS*DD];
__device__ float g_K[BH*SS*DD];
__device__ float g_V[BH*SS*DD];
__device__ float g_posK[HH*PP*DD];
__device__ float g_posQ[HH*PP*DD];
__device__ float g_C2P[(size_t)BH*SS*PP];
__device__ float g_P2C[(size_t)BH*SS*PP];
__device__ float g_S[(size_t)BH*SS*SS];
__device__ float g_ctx[BB*SS*DMODEL];
__device__ float g_H[BB*SS*DMODEL];
__device__ int   g_idx[2047];

// ---------------- idx table: clip(bucket(delta)+256, 0, 511) -----------------
__global__ void build_idx_kernel() {
    int t = blockIdx.x * blockDim.x + threadIdx.x;
    if (t >= 2047) return;
    int rel = t - 1023;
    int bucket;
    if (rel > -128 && rel < 128) {
        bucket = rel;
    } else {
        double abs_pos = fabs((double)rel);
        if (abs_pos <= 128.0) {
            bucket = rel;
        } else {
            int sgn = (rel > 0) - (rel < 0);
            double lp = ceil(log(abs_pos / 128.0) / log(511.0 / 128.0) * 127.0) + 128.0;
            bucket = (int)lp * sgn;
        }
    }
    int i1 = bucket + 256;
    i1 = i1 < 0 ? 0 : (i1 > 511 ? 511 : i1);
    g_idx[t] = i1;
}

// k-pair permutation within a 32-wide k tile: octet j -> (j<4 ? 2j : 2(j-4)+1)
// so frag cols (c, c+4) sit adjacent -> LDS.64 fragment loads.
__device__ __forceinline__ int KP(int k) {
    return (k & 24) | ((k & 3) << 1) | ((k & 7) >> 2);
}

__device__ __forceinline__ float to_tf32(float x) {
    float y;
    asm("cvt.rna.tf32.f32 %0, %1;" : "=f"(y) : "f"(x));
    return y;
}

__device__ __forceinline__ void mma_tf32(float (&d)[4],
                                         uint32_t a0, uint32_t a1, uint32_t a2, uint32_t a3,
                                         uint32_t b0, uint32_t b1) {
    asm volatile(
        "mma.sync.aligned.m16n8k8.row.col.f32.tf32.tf32.f32 "
        "{%0,%1,%2,%3}, {%4,%5,%6,%7}, {%8,%9}, {%0,%1,%2,%3};\n"
        : "+f"(d[0]), "+f"(d[1]), "+f"(d[2]), "+f"(d[3])
        : "r"(a0), "r"(a1), "r"(a2), "r"(a3), "r"(b0), "r"(b1));
}

// ============================================================================
// Unified tf32 tensor-core GEMM.
//   C[z] = A[z] (MxK, row-major, lda) @ op(B[z]) + epilogue
//   TRANSB=false: B is KxN row-major (ldb=N-ish).  TRANSB=true: B is NxK row-major.
// Block tile 128 x BN x 32.  8 warps: warp_m in {0,1} (64 rows), warp_n in 0..3.
// Warp tile 64 x (WN8*8).  EPI selects fused epilogue.
//   EPI 0: C += (nothing); plain store to Cout + z*strideCz, ldc
//   EPI 1: qkv head-major scatter with bias: out[((b*16+h)*srows+s)*64+d]
//   EPI 2: C = acc + bias[n] + resid[m*ldc+n] -> Cout row-major
//   EPI 3: scores: (acc + C2P[q][id] + P2C[k][id]) * INV_SCALE -> Cout (g_S)
//   EPI 4: pv -> g_ctx[(b*S+s)*1024 + h*64 + n]
// ============================================================================
template<int BN, int WN8, bool TRANSB, int EPI>
__global__ __launch_bounds__(256) void mm_tf32(
    const float* __restrict__ A, int lda, long long strideAz,
    const float* __restrict__ B, int ldb, long long strideBz, int bmod16,
    float* __restrict__ Cout, int ldc, long long strideCz,
    int M, int N, int K,
    const float* __restrict__ bias,
    const float* __restrict__ resid,
    int srows)
{
    __shared__ __align__(16) float sA[128][34];
    __shared__ __align__(16) float sB[BN][34];

    const int z = blockIdx.z;
    A += (size_t)z * strideAz;
    B += (size_t)(bmod16 ? (z % HH) : z) * strideBz;

    const int tid  = threadIdx.x;
    const int wid  = tid >> 5, lane = tid & 31;
    const int wm   = wid & 1,  wn   = wid >> 1;
    const int r    = lane >> 2, cq  = lane & 3;
    const int m0   = blockIdx.y * 128;
    const int n0   = blockIdx.x * BN;

    float c[4][WN8][4];
    #pragma unroll
    for (int mt = 0; mt < 4; mt++)
        #pragma unroll
        for (int nt = 0; nt < WN8; nt++)
            #pragma unroll
            for (int q = 0; q < 4; q++) c[mt][nt][q] = 0.f;

    for (int k0 = 0; k0 < K; k0 += 32) {
        // ---- load A tile 128x32 (row-major), store k-permuted ----
        #pragma unroll
        for (int i = 0; i < 4; i++) {
            int idx = i * 256 + tid;          // 0..1023 float4s
            int row = idx >> 3;
            int col4 = (idx & 7) << 2;
            float4 v = *(const float4*)(A + (size_t)(m0 + row) * lda + k0 + col4);
            sA[row][KP(col4 + 0)] = to_tf32(v.x);
            sA[row][KP(col4 + 1)] = to_tf32(v.y);
            sA[row][KP(col4 + 2)] = to_tf32(v.z);
            sA[row][KP(col4 + 3)] = to_tf32(v.w);
        }
        // ---- load B tile ----
        if (TRANSB) {
            // B: N x K row-major -> tile BN x 32 (same shape as A)
            #pragma unroll
            for (int i = 0; i < BN / 32; i++) {
                int idx = i * 256 + tid;
                int row = idx >> 3;
                int col4 = (idx & 7) << 2;
                float4 v = *(const float4*)(B + (size_t)(n0 + row) * ldb + k0 + col4);
                sB[row][KP(col4 + 0)] = to_tf32(v.x);
                sB[row][KP(col4 + 1)] = to_tf32(v.y);
                sB[row][KP(col4 + 2)] = to_tf32(v.z);
                sB[row][KP(col4 + 3)] = to_tf32(v.w);
            }
        } else {
            // B: K x N row-major -> tile 32 x BN, transpose into sB[n][k']
            if (BN == 128) {
                #pragma unroll
                for (int i = 0; i < 4; i++) {
                    int idx = i * 256 + tid;
                    int kr = idx >> 5;
                    int n4 = (idx & 31) << 2;
                    float4 v = *(const float4*)(B + (size_t)(k0 + kr) * ldb + n0 + n4);
                    int kp = KP(kr);
                    sB[n4 + 0][kp] = to_tf32(v.x);
                    sB[n4 + 1][kp] = to_tf32(v.y);
                    sB[n4 + 2][kp] = to_tf32(v.z);
                    sB[n4 + 3][kp] = to_tf32(v.w);
                }
            } else { // BN == 64
                #pragma unroll
                for (int i = 0; i < 2; i++) {
                    int idx = i * 256 + tid;
                    int kr = idx >> 4;
                    int n4 = (idx & 15) << 2;
                    float4 v = *(const float4*)(B + (size_t)(k0 + kr) * ldb + n0 + n4);
                    int kp = KP(kr);
                    sB[n4 + 0][kp] = to_tf32(v.x);
                    sB[n4 + 1][kp] = to_tf32(v.y);
                    sB[n4 + 2][kp] = to_tf32(v.z);
                    sB[n4 + 3][kp] = to_tf32(v.w);
                }
            }
        }
        __syncthreads();

        // ---- 4 k-steps of m16n8k8 ----
        #pragma unroll
        for (int ks = 0; ks < 4; ks++) {
            float2 afr[4][2];
            #pragma unroll
            for (int mt = 0; mt < 4; mt++) {
                int mrow = wm * 64 + mt * 16 + r;
                afr[mt][0] = *(const float2*)&sA[mrow][ks * 8 + 2 * cq];
                afr[mt][1] = *(const float2*)&sA[mrow + 8][ks * 8 + 2 * cq];
            }
            float2 bfr[WN8];
            #pragma unroll
            for (int nt = 0; nt < WN8; nt++)
                bfr[nt] = *(const float2*)&sB[wn * WN8 * 8 + nt * 8 + r][ks * 8 + 2 * cq];
            #pragma unroll
            for (int mt = 0; mt < 4; mt++) {
                uint32_t a0 = __float_as_uint(afr[mt][0].x);
                uint32_t a1 = __float_as_uint(afr[mt][1].x);
                uint32_t a2 = __float_as_uint(afr[mt][0].y);
                uint32_t a3 = __float_as_uint(afr[mt][1].y);
                #pragma unroll
                for (int nt = 0; nt < WN8; nt++)
                    mma_tf32(c[mt][nt], a0, a1, a2, a3,
                             __float_as_uint(bfr[nt].x), __float_as_uint(bfr[nt].y));
            }
        }
        __syncthreads();
    }

    // ---- epilogue ----
    float* Cz = Cout + (size_t)z * strideCz;
    #pragma unroll
    for (int mt = 0; mt < 4; mt++) {
        #pragma unroll
        for (int e = 0; e < 2; e++) {
            int gm = m0 + wm * 64 + mt * 16 + r + e * 8;
            #pragma unroll
            for (int nt = 0; nt < WN8; nt++) {
                int gn = n0 + wn * WN8 * 8 + nt * 8 + 2 * cq;
                float v0 = c[mt][nt][e * 2 + 0];
                float v1 = c[mt][nt][e * 2 + 1];
                if (EPI == 0) {
                    float2 o = {v0, v1};
                    *(float2*)(Cz + (size_t)gm * ldc + gn) = o;
                } else if (EPI == 1) {
                    int h = gn >> 6, d = gn & 63;
                    int b = gm / srows, s = gm % srows;
                    float2 o = {v0 + bias[gn], v1 + bias[gn + 1]};
                    *(float2*)(Cout + ((((size_t)b * HH + h) * srows + s) << 6) + d) = o;
                } else if (EPI == 2) {
                    size_t a = (size_t)gm * ldc + gn;
                    float2 rr = *(const float2*)(resid + a);
                    float2 o = {v0 + bias[gn] + rr.x, v1 + bias[gn + 1] + rr.y};
                    *(float2*)(Cout + a) = o;
                } else if (EPI == 3) {
                    int id0 = g_idx[gm - gn + 1023];
                    int id1 = g_idx[gm - gn + 1022];
                    size_t cb = ((size_t)z * SS + gm) * PP;
                    float o0 = (v0 + g_C2P[cb + id0]
                                + g_P2C[((size_t)z * SS + gn) * PP + id0]) * INV_SCALE;
                    float o1 = (v1 + g_C2P[cb + id1]
                                + g_P2C[((size_t)z * SS + gn + 1) * PP + id1]) * INV_SCALE;
                    float2 o = {o0, o1};
                    *(float2*)(Cz + (size_t)gm * ldc + gn) = o;
                } else { // EPI == 4
                    int b = z >> 4, h = z & 15;
                    float2 o = {v0, v1};
                    *(float2*)(Cout + ((size_t)(b * SS + gm) * DMODEL) + h * DD + gn) = o;
                }
            }
        }
    }
}

// ---------------- masked softmax over k, in place in g_S ---------------------
__global__ __launch_bounds__(256) void softmax_kernel(const int* __restrict__ am)
{
    __shared__ float red[256];
    int row = blockIdx.x;              // bh*S + q
    int bh = row >> 10, q = row & 1023;
    int b = bh >> 4;
    float* srow = g_S + (size_t)row * SS;
    const int* mrow = am + ((size_t)(b * SS + q)) * SS;
    int t = threadIdx.x;
    float x[4]; int m[4];
    float mx = -3.0e38f;
    #pragma unroll
    for (int i = 0; i < 4; i++) {
        int k = t + i * 256;
        m[i] = mrow[k];
        x[i] = m[i] ? srow[k] : -3.0e38f;
        mx = fmaxf(mx, x[i]);
    }
    red[t] = mx; __syncthreads();
    for (int s = 128; s; s >>= 1) { if (t < s) red[t] = fmaxf(red[t], red[t + s]); __syncthreads(); }
    mx = red[0]; __syncthreads();
    float sm = 0.f;
    #pragma unroll
    for (int i = 0; i < 4; i++) {
        x[i] = m[i] ? __expf(x[i] - mx) : 0.f;
        sm += x[i];
    }
    red[t] = sm; __syncthreads();
    for (int s = 128; s; s >>= 1) { if (t < s) red[t] += red[t + s]; __syncthreads(); }
    float inv = red[0] > 0.f ? 1.f / red[0] : 0.f;
    #pragma unroll
    for (int i = 0; i < 4; i++) srow[t + i * 256] = x[i] * inv;
}

// ---------------- layernorm of g_H, write to output --------------------------
__global__ __launch_bounds__(256) void ln_kernel(
    const float* __restrict__ lw, const float* __restrict__ lb,
    float* __restrict__ out)
{
    __shared__ float red[256];
    __shared__ float red2[256];
    int r = blockIdx.x, t = threadIdx.x;
    const float* x = g_H + (size_t)r * DMODEL;
    float s = 0.f, s2 = 0.f;
    #pragma unroll
    for (int i = 0; i < 4; i++) {
        float v = x[t + i * 256];
        s += v; s2 += v * v;
    }
    red[t] = s; red2[t] = s2; __syncthreads();
    for (int st = 128; st; st >>= 1) {
        if (t < st) { red[t] += red[t + st]; red2[t] += red2[t + st]; }
        __syncthreads();
    }
    float mu = red[0] * (1.f / DMODEL);
    float var = red2[0] * (1.f / DMODEL) - mu * mu;
    float inv = rsqrtf(var + 1e-7f);
    #pragma unroll
    for (int i = 0; i < 4; i++) {
        int c = t + i * 256;
        out[(size_t)r * DMODEL + c] = (x[c] - mu) * inv * lw[c] + lb[c];
    }
}

// ---------------- launch ------------------------------------------------------
extern "C" void kernel_launch(void* const* d_in, const int* in_sizes, int n_in,
                              void* d_out, int out_size)
{
    const float* hs  = (const float*)d_in[0];
    const float* rel = (const float*)d_in[1];
    const float* Wq  = (const float*)d_in[2];  const float* bq = (const float*)d_in[3];
    const float* Wk  = (const float*)d_in[4];  const float* bk = (const float*)d_in[5];
    const float* Wv  = (const float*)d_in[6];  const float* bv = (const float*)d_in[7];
    const float* Wo  = (const float*)d_in[8];  const float* bo = (const float*)d_in[9];
    const float* lw  = (const float*)d_in[10]; const float* lb = (const float*)d_in[11];
    const int*   am  = (const int*)d_in[12];
    float* out = (float*)d_out;

    float *Q_, *K_, *V_, *PK_, *PQ_, *C2P_, *P2C_, *S_, *CTX_, *Hb_;
    cudaGetSymbolAddress((void**)&Q_,   g_Q);
    cudaGetSymbolAddress((void**)&K_,   g_K);
    cudaGetSymbolAddress((void**)&V_,   g_V);
    cudaGetSymbolAddress((void**)&PK_,  g_posK);
    cudaGetSymbolAddress((void**)&PQ_,  g_posQ);
    cudaGetSymbolAddress((void**)&C2P_, g_C2P);
    cudaGetSymbolAddress((void**)&P2C_, g_P2C);
    cudaGetSymbolAddress((void**)&S_,   g_S);
    cudaGetSymbolAddress((void**)&CTX_, g_ctx);
    cudaGetSymbolAddress((void**)&Hb_,  g_H);

    build_idx_kernel<<<8, 256>>>();

    // projections -> head-major Q/K/V  [BH][S][64]
    mm_tf32<128,4,false,1><<<dim3(8,16,1),256>>>(hs,1024,0, Wq,1024,0,0, Q_,0,0, 2048,1024,1024, bq,nullptr, SS);
    mm_tf32<128,4,false,1><<<dim3(8,16,1),256>>>(hs,1024,0, Wk,1024,0,0, K_,0,0, 2048,1024,1024, bk,nullptr, SS);
    mm_tf32<128,4,false,1><<<dim3(8,16,1),256>>>(hs,1024,0, Wv,1024,0,0, V_,0,0, 2048,1024,1024, bv,nullptr, SS);
    // position projections -> head-major [H][512][64]
    mm_tf32<128,4,false,1><<<dim3(8,4,1),256>>>(rel,1024,0, Wk,1024,0,0, PK_,0,0, 512,1024,1024, bk,nullptr, PP);
    mm_tf32<128,4,false,1><<<dim3(8,4,1),256>>>(rel,1024,0, Wq,1024,0,0, PQ_,0,0, 512,1024,1024, bq,nullptr, PP);

    // disentangled bias tables: C2P = Q @ posK^T, P2C = K @ posQ^T  (per bh)
    mm_tf32<128,4,true,0><<<dim3(4,8,32),256>>>(Q_,64,(long long)SS*DD, PK_,64,(long long)PP*DD,1,
                                                C2P_,PP,(long long)SS*PP, 1024,512,64, nullptr,nullptr,0);
    mm_tf32<128,4,true,0><<<dim3(4,8,32),256>>>(K_,64,(long long)SS*DD, PQ_,64,(long long)PP*DD,1,
                                                P2C_,PP,(long long)SS*PP, 1024,512,64, nullptr,nullptr,0);

    // scores = (Q K^T + gathers) * INV_SCALE
    mm_tf32<128,4,true,3><<<dim3(8,8,32),256>>>(Q_,64,(long long)SS*DD, K_,64,(long long)SS*DD,0,
                                                S_,SS,(long long)SS*SS, 1024,1024,64, nullptr,nullptr,0);
    softmax_kernel<<<BH*SS, 256>>>(am);

    // ctx = probs @ V  -> [B,S,DM] interleaved
    mm_tf32<64,2,false,4><<<dim3(1,8,32),256>>>(S_,1024,(long long)SS*SS, V_,64,(long long)SS*DD,0,
                                                CTX_,0,0, 1024,64,1024, nullptr,nullptr,0);

    // output projection + residual, then layernorm
    mm_tf32<128,4,false,2><<<dim3(8,16,1),256>>>(CTX_,1024,0, Wo,1024,0,0, Hb_,1024,0,
                                                 2048,1024,1024, bo,hs,0);
    ln_kernel<<<BB*SS, 256>>>(lw, lb, out);
}

// round 4
// speedup vs baseline: 2.7514x; 1.8905x over previous
#include <cuda_runtime.h>
#include <math.h>
#include <stdint.h>

#define BB 2
#define SS 1024
#define DMODEL 1024
#define HH 16
#define DD 64
#define PP 512               // 2*SPAN
#define BH (BB*HH)
#define INV_SCALE 0.07216878364870323f   // 1/sqrt(192)
#define STAGES 3

// ---------------- scratch (static device memory; no allocs allowed) ----------
__device__ float g_Q[BH*SS*DD];      // [bh][s][64]
__device__ float g_K[BH*SS*DD];
__device__ float g_V[BH*SS*DD];
__device__ float g_Vt[BH*DD*SS];     // [bh][64][s]
__device__ float g_posK[HH*PP*DD];   // [h][p][64]
__device__ float g_posQ[HH*PP*DD];
__device__ float g_Wt[4u*DMODEL*DMODEL]; // Wq^T, Wk^T, Wv^T, Wo^T
__device__ float g_C2P[(size_t)BH*SS*PP];
__device__ float g_P2C[(size_t)BH*SS*PP];
__device__ float g_S[(size_t)BH*SS*SS];
__device__ float g_ctx[BB*SS*DMODEL];
__device__ float g_H[BB*SS*DMODEL];
__device__ int   g_idx[2047];

// ---------------- idx table: clip(bucket(delta)+256, 0, 511) -----------------
__global__ void build_idx_kernel() {
    int t = blockIdx.x * blockDim.x + threadIdx.x;
    if (t >= 2047) return;
    int rel = t - 1023;
    int bucket;
    if (rel > -128 && rel < 128) {
        bucket = rel;
    } else {
        double abs_pos = fabs((double)rel);
        if (abs_pos <= 128.0) {
            bucket = rel;
        } else {
            int sgn = (rel > 0) - (rel < 0);
            double lp = ceil(log(abs_pos / 128.0) / log(511.0 / 128.0) * 127.0) + 128.0;
            bucket = (int)lp * sgn;
        }
    }
    int i1 = bucket + 256;
    i1 = i1 < 0 ? 0 : (i1 > 511 ? 511 : i1);
    g_idx[t] = i1;
}

__device__ __forceinline__ float to_tf32(float x) {
    float y;
    asm("cvt.rna.tf32.f32 %0, %1;" : "=f"(y) : "f"(x));
    return y;
}

__device__ __forceinline__ void mma_tf32(float (&d)[4],
                                         uint32_t a0, uint32_t a1, uint32_t a2, uint32_t a3,
                                         uint32_t b0, uint32_t b1) {
    asm volatile(
        "mma.sync.aligned.m16n8k8.row.col.f32.tf32.tf32.f32 "
        "{%0,%1,%2,%3}, {%4,%5,%6,%7}, {%8,%9}, {%0,%1,%2,%3};\n"
        : "+f"(d[0]), "+f"(d[1]), "+f"(d[2]), "+f"(d[3])
        : "r"(a0), "r"(a1), "r"(a2), "r"(a3), "r"(b0), "r"(b1));
}

__device__ __forceinline__ void cpa16(uint32_t s, const float* g) {
    asm volatile("cp.async.cg.shared.global [%0], [%1], 16;\n" :: "r"(s), "l"(g));
}
#define CP_COMMIT() asm volatile("cp.async.commit_group;\n" ::: "memory")
#define CP_WAIT1()  asm volatile("cp.async.wait_group 1;\n" ::: "memory")

// ============================================================================
// NT tf32 GEMM, 3-stage cp.async pipeline, XOR-swizzled smem.
//   C[z] = A[z] (MxK row-major) @ B[z] (NxK row-major)^T + epilogue
// Block 128 x BN x 32, 8 warps (2 x 4), warp tile 64 x (WN8*8).
// EPI 0: plain store      EPI 1: head-major scatter + bias (z selects B/bias/O)
// EPI 2: +bias+resid      EPI 3: scores (+bias gathers)*scale    EPI 4: pv->ctx
// ============================================================================
template<int BN, int EPI>
__global__ __launch_bounds__(256) void mm_nt(
    const float* __restrict__ A, int lda, long long sAz,
    const float* __restrict__ B0, const float* __restrict__ B1, const float* __restrict__ B2,
    int ldb, long long sBz, int bmod16,
    float* __restrict__ O0, float* __restrict__ O1, float* __restrict__ O2,
    int ldc, long long sCz, int K,
    const float* __restrict__ bias0, const float* __restrict__ bias1, const float* __restrict__ bias2,
    const float* __restrict__ resid, int srows)
{
    constexpr int WN8 = BN / 32;
    constexpr int AF = 128 * 32;     // floats per A stage
    constexpr int BF = BN * 32;
    extern __shared__ float sm[];
    float* sA = sm;
    float* sB = sm + STAGES * AF;

    const int z = blockIdx.z;
    const float* Bsel = B0; const float* bias = bias0; float* Osel = O0;
    if (EPI == 1) {
        if (z == 1)      { Bsel = B1; bias = bias1; Osel = O1; }
        else if (z == 2) { Bsel = B2; bias = bias2; Osel = O2; }
    }
    const float* Ag = A + (size_t)z * sAz;
    const float* Bg = Bsel + (size_t)(bmod16 ? (z & 15) : z) * sBz;

    const int tid = threadIdx.x;
    const int m0 = blockIdx.y * 128, n0 = blockIdx.x * BN;
    const uint32_t sA_u = (uint32_t)__cvta_generic_to_shared(sA);
    const uint32_t sB_u = (uint32_t)__cvta_generic_to_shared(sB);

    const int wid = tid >> 5, lane = tid & 31;
    const int wm = wid & 1, wn = wid >> 1;
    const int r = lane >> 2, cq = lane & 3;

    float acc[4][WN8][4];
    #pragma unroll
    for (int mt = 0; mt < 4; mt++)
        #pragma unroll
        for (int nt = 0; nt < WN8; nt++)
            #pragma unroll
            for (int q = 0; q < 4; q++) acc[mt][nt][q] = 0.f;

    auto loadStage = [&](int st, int k0) {
        #pragma unroll
        for (int i = 0; i < 4; i++) {
            int id = tid + i * 256;
            int row = id >> 3, c = id & 7;
            uint32_t dst = sA_u + (uint32_t)((st * AF + row * 32 + ((c ^ (row & 7)) << 2)) << 2);
            cpa16(dst, Ag + (size_t)(m0 + row) * lda + k0 + (c << 2));
        }
        #pragma unroll
        for (int i = 0; i < BN / 32; i++) {
            int id = tid + i * 256;
            int row = id >> 3, c = id & 7;
            uint32_t dst = sB_u + (uint32_t)((st * BF + row * 32 + ((c ^ (row & 7)) << 2)) << 2);
            cpa16(dst, Bg + (size_t)(n0 + row) * ldb + k0 + (c << 2));
        }
    };

    const int nk = K >> 5;
    loadStage(0, 0);  CP_COMMIT();
    loadStage(1, 32); CP_COMMIT();

    for (int it = 0; it < nk; it++) {
        CP_WAIT1();
        __syncthreads();
        int nxt = it + 2;
        if (nxt < nk) loadStage(nxt % STAGES, nxt * 32);
        CP_COMMIT();

        const float* a = sA + (it % STAGES) * AF;
        const float* b = sB + (it % STAGES) * BF;
        #pragma unroll
        for (int ks = 0; ks < 4; ks++) {
            uint32_t af0[4], af1[4], af2[4], af3[4];
            #pragma unroll
            for (int mt = 0; mt < 4; mt++) {
                int R = wm * 64 + mt * 16 + r;
                int r7 = R & 7;
                int lo = ((2 * ks) ^ r7) << 2, hi = ((2 * ks + 1) ^ r7) << 2;
                af0[mt] = __float_as_uint(a[R * 32 + lo + cq]);
                af2[mt] = __float_as_uint(a[R * 32 + hi + cq]);
                af1[mt] = __float_as_uint(a[(R + 8) * 32 + lo + cq]);
                af3[mt] = __float_as_uint(a[(R + 8) * 32 + hi + cq]);
            }
            #pragma unroll
            for (int nt = 0; nt < WN8; nt++) {
                int Nn = wn * WN8 * 8 + nt * 8 + r;
                int n7 = Nn & 7;
                int lo = ((2 * ks) ^ n7) << 2, hi = ((2 * ks + 1) ^ n7) << 2;
                uint32_t b0 = __float_as_uint(b[Nn * 32 + lo + cq]);
                uint32_t b1 = __float_as_uint(b[Nn * 32 + hi + cq]);
                #pragma unroll
                for (int mt = 0; mt < 4; mt++)
                    mma_tf32(acc[mt][nt], af0[mt], af1[mt], af2[mt], af3[mt], b0, b1);
            }
        }
    }

    // ---- epilogue ----
    float* Cz = Osel + (size_t)z * sCz;
    #pragma unroll
    for (int mt = 0; mt < 4; mt++) {
        #pragma unroll
        for (int e = 0; e < 2; e++) {
            int gm = m0 + wm * 64 + mt * 16 + r + e * 8;
            #pragma unroll
            for (int nt = 0; nt < WN8; nt++) {
                int gn = n0 + wn * WN8 * 8 + nt * 8 + 2 * cq;
                float v0 = acc[mt][nt][e * 2 + 0];
                float v1 = acc[mt][nt][e * 2 + 1];
                if (EPI == 0) {
                    float2 o = {v0, v1};
                    *(float2*)(Cz + (size_t)gm * ldc + gn) = o;
                } else if (EPI == 1) {
                    int h = gn >> 6, d = gn & 63;
                    int b = gm / srows, s = gm % srows;
                    float2 o = {v0 + bias[gn], v1 + bias[gn + 1]};
                    *(float2*)(Osel + ((((size_t)b * HH + h) * srows + s) << 6) + d) = o;
                } else if (EPI == 2) {
                    size_t ad = (size_t)gm * ldc + gn;
                    float2 rr = *(const float2*)(resid + ad);
                    float2 o = {v0 + bias[gn] + rr.x, v1 + bias[gn + 1] + rr.y};
                    *(float2*)(Osel + ad) = o;
                } else if (EPI == 3) {
                    int id0 = g_idx[gm - gn + 1023];
                    int id1 = g_idx[gm - gn + 1022];
                    size_t cb = ((size_t)z * SS + gm) * PP;
                    float o0 = (v0 + g_C2P[cb + id0]
                                + g_P2C[((size_t)z * SS + gn) * PP + id0]) * INV_SCALE;
                    float o1 = (v1 + g_C2P[cb + id1]
                                + g_P2C[((size_t)z * SS + gn + 1) * PP + id1]) * INV_SCALE;
                    float2 o = {o0, o1};
                    *(float2*)(Cz + (size_t)gm * ldc + gn) = o;
                } else { // EPI == 4
                    int b = z >> 4, h = z & 15;
                    float2 o = {v0, v1};
                    *(float2*)(O0 + ((size_t)(b * SS + gm) * DMODEL) + h * DD + gn) = o;
                }
            }
        }
    }
}

// -------- weight transpose (with tf32 rounding): Wt[n][k] = tf32(W[k][n]) ----
__global__ void transpose_w(const float* __restrict__ W0, const float* __restrict__ W1,
                            const float* __restrict__ W2, const float* __restrict__ W3)
{
    __shared__ float t[32][33];
    int zz = blockIdx.z;
    const float* W = zz == 0 ? W0 : zz == 1 ? W1 : zz == 2 ? W2 : W3;
    float* Tz = g_Wt + (size_t)zz * DMODEL * DMODEL;
    int x = blockIdx.x * 32 + threadIdx.x;
    int y0 = blockIdx.y * 32;
    #pragma unroll
    for (int i = threadIdx.y; i < 32; i += 8)
        t[i][threadIdx.x] = to_tf32(W[(size_t)(y0 + i) * DMODEL + x]);
    __syncthreads();
    int xo = blockIdx.y * 32 + threadIdx.x;
    int yo0 = blockIdx.x * 32;
    #pragma unroll
    for (int i = threadIdx.y; i < 32; i += 8)
        Tz[(size_t)(yo0 + i) * DMODEL + xo] = t[threadIdx.x][i];
}

// -------- V transpose per head: Vt[bh][d][s] = V[bh][s][d] --------------------
__global__ void transpose_v()
{
    __shared__ float t[32][33];
    int bh = blockIdx.z;
    int s0 = blockIdx.x * 32, d0 = blockIdx.y * 32;
    const float* Vi = g_V + (size_t)bh * SS * DD;
    float* Vo = g_Vt + (size_t)bh * DD * SS;
    #pragma unroll
    for (int i = threadIdx.y; i < 32; i += 8)
        t[i][threadIdx.x] = Vi[(size_t)(s0 + i) * DD + d0 + threadIdx.x];
    __syncthreads();
    #pragma unroll
    for (int i = threadIdx.y; i < 32; i += 8)
        Vo[(size_t)(d0 + i) * SS + s0 + threadIdx.x] = t[threadIdx.x][i];
}

// ---------------- masked softmax over k, in place in g_S ---------------------
__global__ __launch_bounds__(256) void softmax_kernel(const int* __restrict__ am)
{
    __shared__ float red[256];
    int row = blockIdx.x;              // bh*S + q
    int bh = row >> 10, q = row & 1023;
    int b = bh >> 4;
    float* srow = g_S + (size_t)row * SS;
    const int* mrow = am + ((size_t)(b * SS + q)) * SS;
    int t = threadIdx.x;
    float x[4]; int m[4];
    float mx = -3.0e38f;
    #pragma unroll
    for (int i = 0; i < 4; i++) {
        int k = t + i * 256;
        m[i] = mrow[k];
        x[i] = m[i] ? srow[k] : -3.0e38f;
        mx = fmaxf(mx, x[i]);
    }
    red[t] = mx; __syncthreads();
    for (int s = 128; s; s >>= 1) { if (t < s) red[t] = fmaxf(red[t], red[t + s]); __syncthreads(); }
    mx = red[0]; __syncthreads();
    float sm = 0.f;
    #pragma unroll
    for (int i = 0; i < 4; i++) {
        x[i] = m[i] ? __expf(x[i] - mx) : 0.f;
        sm += x[i];
    }
    red[t] = sm; __syncthreads();
    for (int s = 128; s; s >>= 1) { if (t < s) red[t] += red[t + s]; __syncthreads(); }
    float inv = red[0] > 0.f ? 1.f / red[0] : 0.f;
    #pragma unroll
    for (int i = 0; i < 4; i++) srow[t + i * 256] = x[i] * inv;
}

// ---------------- layernorm of g_H, write to output --------------------------
__global__ __launch_bounds__(256) void ln_kernel(
    const float* __restrict__ lw, const float* __restrict__ lb,
    float* __restrict__ out)
{
    __shared__ float red[256];
    __shared__ float red2[256];
    int r = blockIdx.x, t = threadIdx.x;
    const float* x = g_H + (size_t)r * DMODEL;
    float s = 0.f, s2 = 0.f;
    #pragma unroll
    for (int i = 0; i < 4; i++) {
        float v = x[t + i * 256];
        s += v; s2 += v * v;
    }
    red[t] = s; red2[t] = s2; __syncthreads();
    for (int st = 128; st; st >>= 1) {
        if (t < st) { red[t] += red[t + st]; red2[t] += red2[t + st]; }
        __syncthreads();
    }
    float mu = red[0] * (1.f / DMODEL);
    float var = red2[0] * (1.f / DMODEL) - mu * mu;
    float inv = rsqrtf(var + 1e-7f);
    #pragma unroll
    for (int i = 0; i < 4; i++) {
        int c = t + i * 256;
        out[(size_t)r * DMODEL + c] = (x[c] - mu) * inv * lw[c] + lb[c];
    }
}

// ---------------- launch ------------------------------------------------------
extern "C" void kernel_launch(void* const* d_in, const int* in_sizes, int n_in,
                              void* d_out, int out_size)
{
    const float* hs  = (const float*)d_in[0];
    const float* rel = (const float*)d_in[1];
    const float* Wq  = (const float*)d_in[2];  const float* bq = (const float*)d_in[3];
    const float* Wk  = (const float*)d_in[4];  const float* bk = (const float*)d_in[5];
    const float* Wv  = (const float*)d_in[6];  const float* bv = (const float*)d_in[7];
    const float* Wo  = (const float*)d_in[8];  const float* bo = (const float*)d_in[9];
    const float* lw  = (const float*)d_in[10]; const float* lb = (const float*)d_in[11];
    const int*   am  = (const int*)d_in[12];
    float* out = (float*)d_out;

    float *Q_, *K_, *V_, *VT_, *PK_, *PQ_, *WT_, *C2P_, *P2C_, *S_, *CTX_, *Hb_;
    cudaGetSymbolAddress((void**)&Q_,   g_Q);
    cudaGetSymbolAddress((void**)&K_,   g_K);
    cudaGetSymbolAddress((void**)&V_,   g_V);
    cudaGetSymbolAddress((void**)&VT_,  g_Vt);
    cudaGetSymbolAddress((void**)&PK_,  g_posK);
    cudaGetSymbolAddress((void**)&PQ_,  g_posQ);
    cudaGetSymbolAddress((void**)&WT_,  g_Wt);
    cudaGetSymbolAddress((void**)&C2P_, g_C2P);
    cudaGetSymbolAddress((void**)&P2C_, g_P2C);
    cudaGetSymbolAddress((void**)&S_,   g_S);
    cudaGetSymbolAddress((void**)&CTX_, g_ctx);
    cudaGetSymbolAddress((void**)&Hb_,  g_H);

    const float* WtQ = WT_;
    const float* WtK = WT_ + (size_t)1 * DMODEL * DMODEL;
    const float* WtV = WT_ + (size_t)2 * DMODEL * DMODEL;
    const float* WtO = WT_ + (size_t)3 * DMODEL * DMODEL;

    const int SM128 = STAGES * (128 * 32 + 128 * 32) * 4;   // 98304
    const int SM64  = STAGES * (128 * 32 + 64 * 32) * 4;    // 73728
    cudaFuncSetAttribute(mm_nt<128,0>, cudaFuncAttributeMaxDynamicSharedMemorySize, SM128);
    cudaFuncSetAttribute(mm_nt<128,1>, cudaFuncAttributeMaxDynamicSharedMemorySize, SM128);
    cudaFuncSetAttribute(mm_nt<128,2>, cudaFuncAttributeMaxDynamicSharedMemorySize, SM128);
    cudaFuncSetAttribute(mm_nt<128,3>, cudaFuncAttributeMaxDynamicSharedMemorySize, SM128);
    cudaFuncSetAttribute(mm_nt<64,4>,  cudaFuncAttributeMaxDynamicSharedMemorySize, SM64);

    build_idx_kernel<<<8, 256>>>();
    transpose_w<<<dim3(32, 32, 4), dim3(32, 8)>>>(Wq, Wk, Wv, Wo);

    // QKV projections (merged, head-major out)
    mm_nt<128,1><<<dim3(8,16,3),256,SM128>>>(hs,1024,0, WtQ,WtK,WtV, 1024,0,0,
                                             Q_,K_,V_, 0,0, 1024, bq,bk,bv, nullptr, SS);
    transpose_v<<<dim3(32, 2, 32), dim3(32, 8)>>>();

    // position projections (merged)
    mm_nt<128,1><<<dim3(8,4,2),256,SM128>>>(rel,1024,0, WtK,WtQ,nullptr, 1024,0,0,
                                            PK_,PQ_,nullptr, 0,0, 1024, bk,bq,nullptr, nullptr, PP);

    // disentangled bias tables
    mm_nt<128,0><<<dim3(4,8,32),256,SM128>>>(Q_,64,(long long)SS*DD, PK_,nullptr,nullptr,
                                             64,(long long)PP*DD,1,
                                             C2P_,nullptr,nullptr, PP,(long long)SS*PP, 64,
                                             nullptr,nullptr,nullptr, nullptr, 0);
    mm_nt<128,0><<<dim3(4,8,32),256,SM128>>>(K_,64,(long long)SS*DD, PQ_,nullptr,nullptr,
                                             64,(long long)PP*DD,1,
                                             P2C_,nullptr,nullptr, PP,(long long)SS*PP, 64,
                                             nullptr,nullptr,nullptr, nullptr, 0);

    // scores = (Q K^T + gathers) * INV_SCALE
    mm_nt<128,3><<<dim3(8,8,32),256,SM128>>>(Q_,64,(long long)SS*DD, K_,nullptr,nullptr,
                                             64,(long long)SS*DD,0,
                                             S_,nullptr,nullptr, SS,(long long)SS*SS, 64,
                                             nullptr,nullptr,nullptr, nullptr, 0);
    softmax_kernel<<<BH*SS, 256>>>(am);

    // ctx = probs @ V  (B = Vt, NT form)
    mm_nt<64,4><<<dim3(1,8,32),256,SM64>>>(S_,1024,(long long)SS*SS, VT_,nullptr,nullptr,
                                           SS,(long long)DD*SS,0,
                                           CTX_,nullptr,nullptr, 0,0, 1024,
                                           nullptr,nullptr,nullptr, nullptr, 0);

    // output projection + residual, then layernorm
    mm_nt<128,2><<<dim3(8,16,1),256,SM128>>>(CTX_,1024,0, WtO,nullptr,nullptr, 1024,0,0,
                                             Hb_,nullptr,nullptr, 1024,0, 1024,
                                             bo,nullptr,nullptr, hs, 0);
    ln_kernel<<<BB*SS, 256>>>(lw, lb, out);
}